// round 16
// baseline (speedup 1.0000x reference)
#include <cuda_runtime.h>
#include <cuda_fp16.h>
#include <cstdint>

#define D 128
#define MAXN 100000
#define MAXE 1600000

// ---------------- device scratch (allocation-free rule) --------------------
__device__ float g_agg[(size_t)MAXN * D];
__device__ float g_h  [(size_t)MAXN * D];
__device__ float g_t  [(size_t)MAXN * D];
__device__ __half g_xh[(size_t)MAXN * D];   // fp16 mirror of current features
// CSR scratch
__device__ int g_cnt[MAXN];
__device__ int g_off[MAXN + 1];
__device__ int g_cur[MAXN];
__device__ int g_csr[MAXE];
__device__ int g_bsum[128];
__device__ int g_bbase[128];
// 6 GEMMs x single fp16 W^T image, padded row-major [n][136]
#define IMG_ELEMS 17408            // 128 * 136
__device__ __half g_Wimg[6 * IMG_ELEMS];

// ---------------- smem layout for gemm (bytes, per CTA) ---------------------
#define ROWB      272              // 136 halves per row
#define OFF_W     0                // W fp16 image (34816)
#define OFF_AHI   34816            // A hi image, 64 rows (17408)
#define OFF_ALO   52224            // A lo image (17408)
#define OFF_BIAS  69632
#define SMEM_TOTAL 70144           // x3 CTAs = 210432 <= 227KB

#define GEMM_GRID 456              // 3 CTAs x 152 SMs, persistent

__device__ __forceinline__ uint32_t smem_u32(const void* p) {
    uint32_t a;
    asm("{ .reg .u64 t; cvta.to.shared.u64 t, %1; cvt.u32.u64 %0, t; }" : "=r"(a) : "l"(p));
    return a;
}

#define LDSM_X4(r0, r1, r2, r3, addr) \
    asm volatile("ldmatrix.sync.aligned.m8n8.x4.shared.b16 {%0,%1,%2,%3}, [%4];" \
                 : "=r"(r0), "=r"(r1), "=r"(r2), "=r"(r3) : "r"(addr))

#define CP_ASYNC16(dst, src) \
    asm volatile("cp.async.cg.shared.global [%0], [%1], 16;" :: "r"(dst), "l"(src))
#define CP_WAIT() asm volatile("cp.async.wait_all;" ::: "memory")

__device__ __forceinline__ void mma_f16(float* c, const uint32_t* a, uint32_t b0, uint32_t b1) {
    asm volatile(
        "mma.sync.aligned.m16n8k16.row.col.f32.f16.f16.f32 "
        "{%0,%1,%2,%3}, {%4,%5,%6,%7}, {%8,%9}, {%0,%1,%2,%3};"
        : "+f"(c[0]), "+f"(c[1]), "+f"(c[2]), "+f"(c[3])
        : "r"(a[0]), "r"(a[1]), "r"(a[2]), "r"(a[3]), "r"(b0), "r"(b1));
}

// hi/lo fp16 split of 2 floats -> packed half2 regs
__device__ __forceinline__ void split2h(float x0, float x1, uint32_t& hi, uint32_t& lo) {
    __half h0 = __float2half_rn(x0), h1 = __float2half_rn(x1);
    __half l0 = __float2half_rn(x0 - __half2float(h0));
    __half l1 = __float2half_rn(x1 - __half2float(h1));
    __half2 H = __halves2half2(h0, h1), L = __halves2half2(l0, l1);
    hi = *reinterpret_cast<uint32_t*>(&H);
    lo = *reinterpret_cast<uint32_t*>(&L);
}

// ================= CSR build =================================================
__global__ void zero_cnt_kernel(int* cnt, int N) {
    int i = blockIdx.x * blockDim.x + threadIdx.x;
    if (i < N) cnt[i] = 0;
}

__global__ void hist_kernel(const int* __restrict__ ei, int* cnt, int E) {
    int e = blockIdx.x * blockDim.x + threadIdx.x;
    if (e < E) atomicAdd(&cnt[ei[E + e]], 1);
}

__global__ void scan1_kernel(const int* __restrict__ cnt, int* bsum, int N) {
    __shared__ int sh[256];
    int t = threadIdx.x;
    int base = blockIdx.x * 1024 + t * 4;
    int s = 0;
    #pragma unroll
    for (int i = 0; i < 4; i++) { int idx = base + i; if (idx < N) s += cnt[idx]; }
    sh[t] = s;
    __syncthreads();
    for (int off = 128; off > 0; off >>= 1) {
        if (t < off) sh[t] += sh[t + off];
        __syncthreads();
    }
    if (t == 0) bsum[blockIdx.x] = sh[0];
}

__global__ void scan2_kernel(const int* __restrict__ bsum, int* bbase, int NB,
                             int* off, int N, int E) {
    __shared__ int sh[128];
    int t = threadIdx.x;
    int v = (t < NB) ? bsum[t] : 0;
    sh[t] = v;
    __syncthreads();
    #pragma unroll
    for (int d = 1; d < 128; d <<= 1) {
        int u = (t >= d) ? sh[t - d] : 0;
        __syncthreads();
        sh[t] += u;
        __syncthreads();
    }
    if (t < NB) bbase[t] = sh[t] - v;
    if (t == 0) off[N] = E;
}

__global__ void scan3_kernel(const int* __restrict__ cnt, const int* __restrict__ bbase,
                             int* off, int* cur, int N) {
    __shared__ int sh[256];
    int t = threadIdx.x;
    int base = blockIdx.x * 1024 + t * 4;
    int v[4]; int s = 0;
    #pragma unroll
    for (int i = 0; i < 4; i++) {
        int idx = base + i;
        v[i] = (idx < N) ? cnt[idx] : 0;
        s += v[i];
    }
    sh[t] = s;
    __syncthreads();
    #pragma unroll
    for (int d = 1; d < 256; d <<= 1) {
        int u = (t >= d) ? sh[t - d] : 0;
        __syncthreads();
        sh[t] += u;
        __syncthreads();
    }
    int run = bbase[blockIdx.x] + sh[t] - s;
    #pragma unroll
    for (int i = 0; i < 4; i++) {
        int idx = base + i;
        if (idx < N) { off[idx] = run; cur[idx] = run; run += v[i]; }
    }
}

__global__ void fill_kernel(const int* __restrict__ ei, int* cur, int* csr, int E) {
    int e = blockIdx.x * blockDim.x + threadIdx.x;
    if (e < E) {
        int d = ei[E + e];
        int p = atomicAdd(&cur[d], 1);
        csr[p] = ei[e];
    }
}

// ---------------- x -> fp16 mirror -------------------------------------------
__global__ void x2h_kernel(const float* __restrict__ x, __half* __restrict__ xh, int n4) {
    int i = blockIdx.x * blockDim.x + threadIdx.x;
    int stride = gridDim.x * blockDim.x;
    const float4* xr = reinterpret_cast<const float4*>(x);
    uint2* hr = reinterpret_cast<uint2*>(xh);
    for (; i < n4; i += stride) {
        float4 v = xr[i];
        __half2 a = __floats2half2_rn(v.x, v.y);
        __half2 b = __floats2half2_rn(v.z, v.w);
        hr[i] = make_uint2(*reinterpret_cast<uint32_t*>(&a),
                           *reinterpret_cast<uint32_t*>(&b));
    }
}

// ========== aggregation: agg[n] = x[n](fp32) + sum_{s} xh[s](fp16) ===========
// One warp per node; lane owns cols 4L..4L+3 (uint2 of 4 halves per neighbor).
__global__ void agg_csr_kernel(const float* __restrict__ x,
                               const __half* __restrict__ xh,
                               const int* __restrict__ off,
                               const int* __restrict__ csr,
                               float* __restrict__ agg, int M) {
    int warp = (blockIdx.x * blockDim.x + threadIdx.x) >> 5;
    int lane = threadIdx.x & 31;
    if (warp >= M) return;
    int beg = off[warp], end = off[warp + 1];
    const float4* xr = reinterpret_cast<const float4*>(x);
    const uint2* hr = reinterpret_cast<const uint2*>(xh);   // row stride 32 uint2
    float4 sum = xr[(size_t)warp * 32 + lane];
    int e = beg;
    for (; e + 7 < end; e += 8) {
        int s0 = csr[e],     s1 = csr[e + 1], s2 = csr[e + 2], s3 = csr[e + 3];
        int s4 = csr[e + 4], s5 = csr[e + 5], s6 = csr[e + 6], s7 = csr[e + 7];
        uint2 u0 = hr[(size_t)s0 * 32 + lane];
        uint2 u1 = hr[(size_t)s1 * 32 + lane];
        uint2 u2 = hr[(size_t)s2 * 32 + lane];
        uint2 u3 = hr[(size_t)s3 * 32 + lane];
        uint2 u4 = hr[(size_t)s4 * 32 + lane];
        uint2 u5 = hr[(size_t)s5 * 32 + lane];
        uint2 u6 = hr[(size_t)s6 * 32 + lane];
        uint2 u7 = hr[(size_t)s7 * 32 + lane];
        #pragma unroll
        for (int j = 0; j < 8; j++) {
            uint2 u = (j == 0) ? u0 : (j == 1) ? u1 : (j == 2) ? u2 : (j == 3) ? u3
                     : (j == 4) ? u4 : (j == 5) ? u5 : (j == 6) ? u6 : u7;
            float2 fa = __half22float2(*reinterpret_cast<__half2*>(&u.x));
            float2 fb = __half22float2(*reinterpret_cast<__half2*>(&u.y));
            sum.x += fa.x; sum.y += fa.y; sum.z += fb.x; sum.w += fb.y;
        }
    }
    for (; e < end; e++) {
        int s = csr[e];
        uint2 u = hr[(size_t)s * 32 + lane];
        float2 fa = __half22float2(*reinterpret_cast<__half2*>(&u.x));
        float2 fb = __half22float2(*reinterpret_cast<__half2*>(&u.y));
        sum.x += fa.x; sum.y += fa.y; sum.z += fb.x; sum.w += fb.y;
    }
    reinterpret_cast<float4*>(agg)[(size_t)warp * 32 + lane] = sum;
}

// ---------------- W prep: W[k][n] fp32 -> W^T fp16 padded image -------------
struct WPtrs { const float* p[6]; };
__global__ void wprep_kernel(WPtrs wp, __half* img) {
    int t = blockIdx.x * blockDim.x + threadIdx.x;
    if (t >= 6 * 16384) return;
    int g = t >> 14;
    int rem = t & 16383;
    int n = rem >> 7;
    int k = rem & 127;
    img[(size_t)g * IMG_ELEMS + n * 136 + k] = __float2half_rn(wp.p[g][k * D + n]);
}

// ---------------- GEMM: fp16 2-term, persistent, 3 CTAs/SM ------------------
// Grid 456, 256 threads / 8 warps, tile 64x128 per iteration.
// Warp grid 4x2 (16 rows x 64 cols). Pair {w, w+4} shares A rows, splits the
// convert (8 rows each), syncs on named barrier (1+wg_row, 64 threads).
// Numerics: C = (Ahi + Alo) @ Whi, fp16 operands, fp32 accumulate.
// If Ch != null, also writes the fp16 mirror of the output (for next agg).
__global__ __launch_bounds__(256, 3) void gemm_mma_kernel(
    const float* __restrict__ A, const __half* __restrict__ Wimg,
    const float* __restrict__ bias, float* __restrict__ C,
    __half* __restrict__ Ch, int M, int nt) {
    extern __shared__ char smem[];
    uint32_t sb = smem_u32(smem);
    int tid = threadIdx.x, wid = tid >> 5, lane = tid & 31;
    int wg_row = wid & 3, wg_col = wid >> 2;

    // ---- one-time: W fp16 image (34816 B) + bias ----
    {
        const char* src = reinterpret_cast<const char*>(Wimg);
        #pragma unroll
        for (int i = 0; i < 9; i++) {
            int c = tid + i * 256;                 // need < 2176
            if (c < 2176) {
                uint32_t o = (uint32_t)c * 16;
                CP_ASYNC16(sb + OFF_W + o, src + o);
            }
        }
    }
    if (tid < 32)
        reinterpret_cast<float4*>(smem + OFF_BIAS)[tid] =
            reinterpret_cast<const float4*>(bias)[tid];
    CP_WAIT();
    __syncthreads();

    const float* sBias = reinterpret_cast<const float*>(smem + OFF_BIAS);
    uint32_t aBase = sb + OFF_AHI + (wg_row * 16 + (lane & 15)) * ROWB + (lane >> 4) * 16;
    uint32_t wBase = sb + OFF_W
                   + (wg_col * 64 + ((lane >> 4) << 3) + (lane & 7)) * ROWB
                   + ((lane >> 3) & 1) * 16;
    int convBase = wg_row * 16 + wg_col * 8;   // pair splits 16 rows: 8 each

    for (int t = blockIdx.x; t < nt; t += gridDim.x) {
        int row0 = t << 6;

        // ---- convert this pair-half's 8 A rows to fp16 hi/lo ----
        #pragma unroll
        for (int i = 0; i < 8; i++) {
            int trow = convBase + i;
            int grow = row0 + trow;
            uint32_t hi0 = 0, hi1 = 0, lo0 = 0, lo1 = 0;
            if (grow < M) {
                float4 v = reinterpret_cast<const float4*>(A + (size_t)grow * D)[lane];
                split2h(v.x, v.y, hi0, lo0);
                split2h(v.z, v.w, hi1, lo1);
            }
            uint32_t o = (uint32_t)trow * ROWB + (uint32_t)lane * 8;
            *reinterpret_cast<uint2*>(smem + OFF_AHI + o) = make_uint2(hi0, hi1);
            *reinterpret_cast<uint2*>(smem + OFF_ALO + o) = make_uint2(lo0, lo1);
        }
        asm volatile("bar.sync %0, 64;" :: "r"(1 + wg_row) : "memory");

        // ---- mma loop: 2-term fp16 ----
        float acc[8][4];
        #pragma unroll
        for (int nb = 0; nb < 8; nb++)
            #pragma unroll
            for (int j = 0; j < 4; j++) acc[nb][j] = 0.0f;

        #pragma unroll
        for (int kc = 0; kc < 8; kc++) {
            uint32_t aHi[4], aLo[4];
            uint32_t aAddr = aBase + kc * 32;
            LDSM_X4(aHi[0], aHi[1], aHi[2], aHi[3], aAddr);
            LDSM_X4(aLo[0], aLo[1], aLo[2], aLo[3], aAddr + (OFF_ALO - OFF_AHI));
            #pragma unroll
            for (int nbp = 0; nbp < 4; nbp++) {
                uint32_t bAddr = wBase + nbp * (16 * ROWB) + kc * 32;
                uint32_t b0, b1, b2, b3;
                LDSM_X4(b0, b1, b2, b3, bAddr);
                mma_f16(acc[2 * nbp],     aHi, b0, b1);
                mma_f16(acc[2 * nbp],     aLo, b0, b1);
                mma_f16(acc[2 * nbp + 1], aHi, b2, b3);
                mma_f16(acc[2 * nbp + 1], aLo, b2, b3);
            }
        }

        // WAR: pair done reading A before next iteration's convert overwrites
        asm volatile("bar.sync %0, 64;" :: "r"(1 + wg_row) : "memory");

        // ---- epilogue ----
        int r0 = row0 + wg_row * 16 + (lane >> 2);
        int r1 = r0 + 8;
        #pragma unroll
        for (int nb = 0; nb < 8; nb++) {
            int cb = wg_col * 64 + nb * 8 + (lane & 3) * 2;
            float b0 = sBias[cb], b1 = sBias[cb + 1];
            if (r0 < M) {
                float2 o;
                o.x = fmaxf(acc[nb][0] + b0, 0.f);
                o.y = fmaxf(acc[nb][1] + b1, 0.f);
                *reinterpret_cast<float2*>(C + (size_t)r0 * D + cb) = o;
                if (Ch) {
                    __half2 p = __floats2half2_rn(o.x, o.y);
                    *reinterpret_cast<uint32_t*>(Ch + (size_t)r0 * D + cb) =
                        *reinterpret_cast<uint32_t*>(&p);
                }
            }
            if (r1 < M) {
                float2 o;
                o.x = fmaxf(acc[nb][2] + b0, 0.f);
                o.y = fmaxf(acc[nb][3] + b1, 0.f);
                *reinterpret_cast<float2*>(C + (size_t)r1 * D + cb) = o;
                if (Ch) {
                    __half2 p = __floats2half2_rn(o.x, o.y);
                    *reinterpret_cast<uint32_t*>(Ch + (size_t)r1 * D + cb) =
                        *reinterpret_cast<uint32_t*>(&p);
                }
            }
        }
    }
}

extern "C" void kernel_launch(void* const* d_in, const int* in_sizes, int n_in,
                              void* d_out, int out_size) {
    const float* x  = (const float*)d_in[0];
    const int*   ei = (const int*)d_in[1];   // int32 (JAX x64 disabled)
    const float* W1[3] = {(const float*)d_in[2],  (const float*)d_in[6],  (const float*)d_in[10]};
    const float* b1[3] = {(const float*)d_in[3],  (const float*)d_in[7],  (const float*)d_in[11]};
    const float* W2[3] = {(const float*)d_in[4],  (const float*)d_in[8],  (const float*)d_in[12]};
    const float* b2[3] = {(const float*)d_in[5],  (const float*)d_in[9],  (const float*)d_in[13]};

    int M = in_sizes[0] / D;
    int E = in_sizes[1] / 2;

    float *agg, *h, *t;
    __half *wimg, *xh;
    int *cnt, *off, *cur, *csr, *bsum, *bbase;
    cudaGetSymbolAddress((void**)&agg,   g_agg);
    cudaGetSymbolAddress((void**)&h,     g_h);
    cudaGetSymbolAddress((void**)&t,     g_t);
    cudaGetSymbolAddress((void**)&xh,    g_xh);
    cudaGetSymbolAddress((void**)&wimg,  g_Wimg);
    cudaGetSymbolAddress((void**)&cnt,   g_cnt);
    cudaGetSymbolAddress((void**)&off,   g_off);
    cudaGetSymbolAddress((void**)&cur,   g_cur);
    cudaGetSymbolAddress((void**)&csr,   g_csr);
    cudaGetSymbolAddress((void**)&bsum,  g_bsum);
    cudaGetSymbolAddress((void**)&bbase, g_bbase);

    cudaFuncSetAttribute(gemm_mma_kernel, cudaFuncAttributeMaxDynamicSharedMemorySize, SMEM_TOTAL);

    // W images (order: W1_0, W2_0, W1_1, W2_1, W1_2, W2_2)
    WPtrs wp;
    wp.p[0] = W1[0]; wp.p[1] = W2[0];
    wp.p[2] = W1[1]; wp.p[3] = W2[1];
    wp.p[4] = W1[2]; wp.p[5] = W2[2];
    wprep_kernel<<<(6 * 16384 + 255) / 256, 256>>>(wp, wimg);

    // CSR build (edges identical across layers)
    int NB = (M + 1023) / 1024;
    zero_cnt_kernel<<<(M + 255) / 256, 256>>>(cnt, M);
    hist_kernel<<<(E + 255) / 256, 256>>>(ei, cnt, E);
    scan1_kernel<<<NB, 256>>>(cnt, bsum, M);
    scan2_kernel<<<1, 128>>>(bsum, bbase, NB, off, M, E);
    scan3_kernel<<<NB, 256>>>(cnt, bbase, off, cur, M);
    fill_kernel<<<(E + 255) / 256, 256>>>(ei, cur, csr, E);

    int n4 = M * D / 4;
    int convBlocks = (n4 + 255) / 256;
    if (convBlocks > 4096) convBlocks = 4096;
    x2h_kernel<<<convBlocks, 256>>>(x, xh, n4);   // fp16 mirror of layer-0 input

    int aggBlocks = (M * 32 + 255) / 256;
    int nt = (M + 63) / 64;
    int gemmGrid = (nt < GEMM_GRID) ? nt : GEMM_GRID;

    const float* curx = x;
    float* outs[3] = {t, t, (float*)d_out};

    for (int l = 0; l < 3; l++) {
        agg_csr_kernel<<<aggBlocks, 256>>>(curx, xh, off, csr, agg, M);
        gemm_mma_kernel<<<gemmGrid, 256, SMEM_TOTAL>>>(
            agg, wimg + (size_t)(2 * l) * IMG_ELEMS, b1[l], h, nullptr, M, nt);
        // GEMM2 writes fp32 out and (for layers 0,1) the fp16 mirror for next agg
        gemm_mma_kernel<<<gemmGrid, 256, SMEM_TOTAL>>>(
            h, wimg + (size_t)(2 * l + 1) * IMG_ELEMS, b2[l], outs[l],
            (l < 2) ? xh : nullptr, M, nt);
        curx = outs[l];
    }
}

// round 17
// speedup vs baseline: 1.0176x; 1.0176x over previous
#include <cuda_runtime.h>
#include <cuda_fp16.h>
#include <cstdint>

#define D 128
#define MAXN 100000
#define MAXE 1600000

// ---------------- device scratch (allocation-free rule) --------------------
__device__ float g_agg[(size_t)MAXN * D];
__device__ float g_h  [(size_t)MAXN * D];
__device__ float g_t  [(size_t)MAXN * D];
__device__ __half g_xh[(size_t)MAXN * D];   // fp16 mirror of current features
// CSR scratch
__device__ int g_cnt[MAXN];
__device__ int g_off[MAXN + 1];
__device__ int g_cur[MAXN];
__device__ int g_csr[MAXE];
__device__ int g_bsum[128];
__device__ int g_bbase[128];
// 6 GEMMs x single fp16 W^T image, padded row-major [n][136]
#define IMG_ELEMS 17408            // 128 * 136
__device__ __half g_Wimg[6 * IMG_ELEMS];

// ---------------- smem layout for gemm (bytes, per CTA) ---------------------
#define ROWB      272              // 136 halves per row
#define OFF_W     0                // W fp16 image (34816)
#define OFF_AHI   34816            // A hi image, 64 rows (17408)
#define OFF_ALO   52224            // A lo image (17408)
#define OFF_BIAS  69632
#define SMEM_TOTAL 70144           // x3 CTAs = 210432 <= 227KB

#define GEMM_GRID 456              // 3 CTAs x 152 SMs, persistent

__device__ __forceinline__ uint32_t smem_u32(const void* p) {
    uint32_t a;
    asm("{ .reg .u64 t; cvta.to.shared.u64 t, %1; cvt.u32.u64 %0, t; }" : "=r"(a) : "l"(p));
    return a;
}

#define LDSM_X4(r0, r1, r2, r3, addr) \
    asm volatile("ldmatrix.sync.aligned.m8n8.x4.shared.b16 {%0,%1,%2,%3}, [%4];" \
                 : "=r"(r0), "=r"(r1), "=r"(r2), "=r"(r3) : "r"(addr))

#define CP_ASYNC16(dst, src) \
    asm volatile("cp.async.cg.shared.global [%0], [%1], 16;" :: "r"(dst), "l"(src))
#define CP_WAIT() asm volatile("cp.async.wait_all;" ::: "memory")

__device__ __forceinline__ void mma_f16(float* c, const uint32_t* a, uint32_t b0, uint32_t b1) {
    asm volatile(
        "mma.sync.aligned.m16n8k16.row.col.f32.f16.f16.f32 "
        "{%0,%1,%2,%3}, {%4,%5,%6,%7}, {%8,%9}, {%0,%1,%2,%3};"
        : "+f"(c[0]), "+f"(c[1]), "+f"(c[2]), "+f"(c[3])
        : "r"(a[0]), "r"(a[1]), "r"(a[2]), "r"(a[3]), "r"(b0), "r"(b1));
}

// hi/lo fp16 split of 2 floats -> packed half2 regs
__device__ __forceinline__ void split2h(float x0, float x1, uint32_t& hi, uint32_t& lo) {
    __half h0 = __float2half_rn(x0), h1 = __float2half_rn(x1);
    __half l0 = __float2half_rn(x0 - __half2float(h0));
    __half l1 = __float2half_rn(x1 - __half2float(h1));
    __half2 H = __halves2half2(h0, h1), L = __halves2half2(l0, l1);
    hi = *reinterpret_cast<uint32_t*>(&H);
    lo = *reinterpret_cast<uint32_t*>(&L);
}

// ================= CSR build =================================================
__global__ void zero_cnt_kernel(int* cnt, int N) {
    int i = blockIdx.x * blockDim.x + threadIdx.x;
    if (i < N) cnt[i] = 0;
}

__global__ void hist_kernel(const int* __restrict__ ei, int* cnt, int E) {
    int e = blockIdx.x * blockDim.x + threadIdx.x;
    if (e < E) atomicAdd(&cnt[ei[E + e]], 1);
}

__global__ void scan1_kernel(const int* __restrict__ cnt, int* bsum, int N) {
    __shared__ int sh[256];
    int t = threadIdx.x;
    int base = blockIdx.x * 1024 + t * 4;
    int s = 0;
    #pragma unroll
    for (int i = 0; i < 4; i++) { int idx = base + i; if (idx < N) s += cnt[idx]; }
    sh[t] = s;
    __syncthreads();
    for (int off = 128; off > 0; off >>= 1) {
        if (t < off) sh[t] += sh[t + off];
        __syncthreads();
    }
    if (t == 0) bsum[blockIdx.x] = sh[0];
}

__global__ void scan2_kernel(const int* __restrict__ bsum, int* bbase, int NB,
                             int* off, int N, int E) {
    __shared__ int sh[128];
    int t = threadIdx.x;
    int v = (t < NB) ? bsum[t] : 0;
    sh[t] = v;
    __syncthreads();
    #pragma unroll
    for (int d = 1; d < 128; d <<= 1) {
        int u = (t >= d) ? sh[t - d] : 0;
        __syncthreads();
        sh[t] += u;
        __syncthreads();
    }
    if (t < NB) bbase[t] = sh[t] - v;
    if (t == 0) off[N] = E;
}

__global__ void scan3_kernel(const int* __restrict__ cnt, const int* __restrict__ bbase,
                             int* off, int* cur, int N) {
    __shared__ int sh[256];
    int t = threadIdx.x;
    int base = blockIdx.x * 1024 + t * 4;
    int v[4]; int s = 0;
    #pragma unroll
    for (int i = 0; i < 4; i++) {
        int idx = base + i;
        v[i] = (idx < N) ? cnt[idx] : 0;
        s += v[i];
    }
    sh[t] = s;
    __syncthreads();
    #pragma unroll
    for (int d = 1; d < 256; d <<= 1) {
        int u = (t >= d) ? sh[t - d] : 0;
        __syncthreads();
        sh[t] += u;
        __syncthreads();
    }
    int run = bbase[blockIdx.x] + sh[t] - s;
    #pragma unroll
    for (int i = 0; i < 4; i++) {
        int idx = base + i;
        if (idx < N) { off[idx] = run; cur[idx] = run; run += v[i]; }
    }
}

__global__ void fill_kernel(const int* __restrict__ ei, int* cur, int* csr, int E) {
    int e = blockIdx.x * blockDim.x + threadIdx.x;
    if (e < E) {
        int d = ei[E + e];
        int p = atomicAdd(&cur[d], 1);
        csr[p] = ei[e];
    }
}

// ---------------- x -> fp16 mirror -------------------------------------------
__global__ void x2h_kernel(const float* __restrict__ x, __half* __restrict__ xh, int n4) {
    int i = blockIdx.x * blockDim.x + threadIdx.x;
    int stride = gridDim.x * blockDim.x;
    const float4* xr = reinterpret_cast<const float4*>(x);
    uint2* hr = reinterpret_cast<uint2*>(xh);
    for (; i < n4; i += stride) {
        float4 v = xr[i];
        __half2 a = __floats2half2_rn(v.x, v.y);
        __half2 b = __floats2half2_rn(v.z, v.w);
        hr[i] = make_uint2(*reinterpret_cast<uint32_t*>(&a),
                           *reinterpret_cast<uint32_t*>(&b));
    }
}

// ========== aggregation: agg[n] = x[n](fp32) + sum_{s} xh[s](fp16) ===========
// TWO nodes per warp: lanes 0-15 -> node 2w, lanes 16-31 -> node 2w+1.
// Each lane owns 8 columns (uint4 = 16B fp16). One warp LDG.128 gathers two
// edges' rows at once; per-half index loads are broadcasts.
__global__ void agg_csr_kernel(const float* __restrict__ x,
                               const __half* __restrict__ xh,
                               const int* __restrict__ off,
                               const int* __restrict__ csr,
                               float* __restrict__ agg, int M) {
    int gw = (blockIdx.x * blockDim.x + threadIdx.x) >> 5;
    int lane = threadIdx.x & 31;
    int half = lane >> 4;
    int hl = lane & 15;
    int node = gw * 2 + half;
    bool valid = node < M;

    int beg = 0, end = 0;
    if (valid) { beg = __ldg(&off[node]); end = __ldg(&off[node + 1]); }

    // self term (fp32)
    float s0f = 0.f, s1f = 0.f, s2f = 0.f, s3f = 0.f,
          s4f = 0.f, s5f = 0.f, s6f = 0.f, s7f = 0.f;
    if (valid) {
        const float4* xr = reinterpret_cast<const float4*>(x + (size_t)node * D + hl * 8);
        float4 a = xr[0], b = xr[1];
        s0f = a.x; s1f = a.y; s2f = a.z; s3f = a.w;
        s4f = b.x; s5f = b.y; s6f = b.z; s7f = b.w;
    }

    const uint4* hr = reinterpret_cast<const uint4*>(xh);   // row = 16 uint4
    int e = beg;
    for (; e + 3 < end; e += 4) {
        int i0 = __ldg(&csr[e]);
        int i1 = __ldg(&csr[e + 1]);
        int i2 = __ldg(&csr[e + 2]);
        int i3 = __ldg(&csr[e + 3]);
        uint4 u0 = hr[(size_t)i0 * 16 + hl];
        uint4 u1 = hr[(size_t)i1 * 16 + hl];
        uint4 u2 = hr[(size_t)i2 * 16 + hl];
        uint4 u3 = hr[(size_t)i3 * 16 + hl];
        #pragma unroll
        for (int j = 0; j < 4; j++) {
            uint4 u = (j == 0) ? u0 : (j == 1) ? u1 : (j == 2) ? u2 : u3;
            float2 f0 = __half22float2(*reinterpret_cast<__half2*>(&u.x));
            float2 f1 = __half22float2(*reinterpret_cast<__half2*>(&u.y));
            float2 f2 = __half22float2(*reinterpret_cast<__half2*>(&u.z));
            float2 f3 = __half22float2(*reinterpret_cast<__half2*>(&u.w));
            s0f += f0.x; s1f += f0.y; s2f += f1.x; s3f += f1.y;
            s4f += f2.x; s5f += f2.y; s6f += f3.x; s7f += f3.y;
        }
    }
    for (; e < end; e++) {
        int i0 = __ldg(&csr[e]);
        uint4 u = hr[(size_t)i0 * 16 + hl];
        float2 f0 = __half22float2(*reinterpret_cast<__half2*>(&u.x));
        float2 f1 = __half22float2(*reinterpret_cast<__half2*>(&u.y));
        float2 f2 = __half22float2(*reinterpret_cast<__half2*>(&u.z));
        float2 f3 = __half22float2(*reinterpret_cast<__half2*>(&u.w));
        s0f += f0.x; s1f += f0.y; s2f += f1.x; s3f += f1.y;
        s4f += f2.x; s5f += f2.y; s6f += f3.x; s7f += f3.y;
    }

    if (valid) {
        float4* out = reinterpret_cast<float4*>(agg + (size_t)node * D + hl * 8);
        out[0] = make_float4(s0f, s1f, s2f, s3f);
        out[1] = make_float4(s4f, s5f, s6f, s7f);
    }
}

// ---------------- W prep: W[k][n] fp32 -> W^T fp16 padded image -------------
struct WPtrs { const float* p[6]; };
__global__ void wprep_kernel(WPtrs wp, __half* img) {
    int t = blockIdx.x * blockDim.x + threadIdx.x;
    if (t >= 6 * 16384) return;
    int g = t >> 14;
    int rem = t & 16383;
    int n = rem >> 7;
    int k = rem & 127;
    img[(size_t)g * IMG_ELEMS + n * 136 + k] = __float2half_rn(wp.p[g][k * D + n]);
}

// ---------------- GEMM: fp16 2-term, persistent, 3 CTAs/SM ------------------
__global__ __launch_bounds__(256, 3) void gemm_mma_kernel(
    const float* __restrict__ A, const __half* __restrict__ Wimg,
    const float* __restrict__ bias, float* __restrict__ C,
    __half* __restrict__ Ch, int M, int nt) {
    extern __shared__ char smem[];
    uint32_t sb = smem_u32(smem);
    int tid = threadIdx.x, wid = tid >> 5, lane = tid & 31;
    int wg_row = wid & 3, wg_col = wid >> 2;

    // ---- one-time: W fp16 image (34816 B) + bias ----
    {
        const char* src = reinterpret_cast<const char*>(Wimg);
        #pragma unroll
        for (int i = 0; i < 9; i++) {
            int c = tid + i * 256;                 // need < 2176
            if (c < 2176) {
                uint32_t o = (uint32_t)c * 16;
                CP_ASYNC16(sb + OFF_W + o, src + o);
            }
        }
    }
    if (tid < 32)
        reinterpret_cast<float4*>(smem + OFF_BIAS)[tid] =
            reinterpret_cast<const float4*>(bias)[tid];
    CP_WAIT();
    __syncthreads();

    const float* sBias = reinterpret_cast<const float*>(smem + OFF_BIAS);
    uint32_t aBase = sb + OFF_AHI + (wg_row * 16 + (lane & 15)) * ROWB + (lane >> 4) * 16;
    uint32_t wBase = sb + OFF_W
                   + (wg_col * 64 + ((lane >> 4) << 3) + (lane & 7)) * ROWB
                   + ((lane >> 3) & 1) * 16;
    int convBase = wg_row * 16 + wg_col * 8;   // pair splits 16 rows: 8 each

    for (int t = blockIdx.x; t < nt; t += gridDim.x) {
        int row0 = t << 6;

        // ---- convert this pair-half's 8 A rows to fp16 hi/lo ----
        #pragma unroll
        for (int i = 0; i < 8; i++) {
            int trow = convBase + i;
            int grow = row0 + trow;
            uint32_t hi0 = 0, hi1 = 0, lo0 = 0, lo1 = 0;
            if (grow < M) {
                float4 v = reinterpret_cast<const float4*>(A + (size_t)grow * D)[lane];
                split2h(v.x, v.y, hi0, lo0);
                split2h(v.z, v.w, hi1, lo1);
            }
            uint32_t o = (uint32_t)trow * ROWB + (uint32_t)lane * 8;
            *reinterpret_cast<uint2*>(smem + OFF_AHI + o) = make_uint2(hi0, hi1);
            *reinterpret_cast<uint2*>(smem + OFF_ALO + o) = make_uint2(lo0, lo1);
        }
        asm volatile("bar.sync %0, 64;" :: "r"(1 + wg_row) : "memory");

        // ---- mma loop: 2-term fp16 ----
        float acc[8][4];
        #pragma unroll
        for (int nb = 0; nb < 8; nb++)
            #pragma unroll
            for (int j = 0; j < 4; j++) acc[nb][j] = 0.0f;

        #pragma unroll
        for (int kc = 0; kc < 8; kc++) {
            uint32_t aHi[4], aLo[4];
            uint32_t aAddr = aBase + kc * 32;
            LDSM_X4(aHi[0], aHi[1], aHi[2], aHi[3], aAddr);
            LDSM_X4(aLo[0], aLo[1], aLo[2], aLo[3], aAddr + (OFF_ALO - OFF_AHI));
            #pragma unroll
            for (int nbp = 0; nbp < 4; nbp++) {
                uint32_t bAddr = wBase + nbp * (16 * ROWB) + kc * 32;
                uint32_t b0, b1, b2, b3;
                LDSM_X4(b0, b1, b2, b3, bAddr);
                mma_f16(acc[2 * nbp],     aHi, b0, b1);
                mma_f16(acc[2 * nbp],     aLo, b0, b1);
                mma_f16(acc[2 * nbp + 1], aHi, b2, b3);
                mma_f16(acc[2 * nbp + 1], aLo, b2, b3);
            }
        }

        // WAR: pair done reading A before next iteration's convert overwrites
        asm volatile("bar.sync %0, 64;" :: "r"(1 + wg_row) : "memory");

        // ---- epilogue ----
        int r0 = row0 + wg_row * 16 + (lane >> 2);
        int r1 = r0 + 8;
        #pragma unroll
        for (int nb = 0; nb < 8; nb++) {
            int cb = wg_col * 64 + nb * 8 + (lane & 3) * 2;
            float b0 = sBias[cb], b1 = sBias[cb + 1];
            if (r0 < M) {
                float2 o;
                o.x = fmaxf(acc[nb][0] + b0, 0.f);
                o.y = fmaxf(acc[nb][1] + b1, 0.f);
                *reinterpret_cast<float2*>(C + (size_t)r0 * D + cb) = o;
                if (Ch) {
                    __half2 p = __floats2half2_rn(o.x, o.y);
                    *reinterpret_cast<uint32_t*>(Ch + (size_t)r0 * D + cb) =
                        *reinterpret_cast<uint32_t*>(&p);
                }
            }
            if (r1 < M) {
                float2 o;
                o.x = fmaxf(acc[nb][2] + b0, 0.f);
                o.y = fmaxf(acc[nb][3] + b1, 0.f);
                *reinterpret_cast<float2*>(C + (size_t)r1 * D + cb) = o;
                if (Ch) {
                    __half2 p = __floats2half2_rn(o.x, o.y);
                    *reinterpret_cast<uint32_t*>(Ch + (size_t)r1 * D + cb) =
                        *reinterpret_cast<uint32_t*>(&p);
                }
            }
        }
    }
}

extern "C" void kernel_launch(void* const* d_in, const int* in_sizes, int n_in,
                              void* d_out, int out_size) {
    const float* x  = (const float*)d_in[0];
    const int*   ei = (const int*)d_in[1];   // int32 (JAX x64 disabled)
    const float* W1[3] = {(const float*)d_in[2],  (const float*)d_in[6],  (const float*)d_in[10]};
    const float* b1[3] = {(const float*)d_in[3],  (const float*)d_in[7],  (const float*)d_in[11]};
    const float* W2[3] = {(const float*)d_in[4],  (const float*)d_in[8],  (const float*)d_in[12]};
    const float* b2[3] = {(const float*)d_in[5],  (const float*)d_in[9],  (const float*)d_in[13]};

    int M = in_sizes[0] / D;
    int E = in_sizes[1] / 2;

    float *agg, *h, *t;
    __half *wimg, *xh;
    int *cnt, *off, *cur, *csr, *bsum, *bbase;
    cudaGetSymbolAddress((void**)&agg,   g_agg);
    cudaGetSymbolAddress((void**)&h,     g_h);
    cudaGetSymbolAddress((void**)&t,     g_t);
    cudaGetSymbolAddress((void**)&xh,    g_xh);
    cudaGetSymbolAddress((void**)&wimg,  g_Wimg);
    cudaGetSymbolAddress((void**)&cnt,   g_cnt);
    cudaGetSymbolAddress((void**)&off,   g_off);
    cudaGetSymbolAddress((void**)&cur,   g_cur);
    cudaGetSymbolAddress((void**)&csr,   g_csr);
    cudaGetSymbolAddress((void**)&bsum,  g_bsum);
    cudaGetSymbolAddress((void**)&bbase, g_bbase);

    cudaFuncSetAttribute(gemm_mma_kernel, cudaFuncAttributeMaxDynamicSharedMemorySize, SMEM_TOTAL);

    // W images (order: W1_0, W2_0, W1_1, W2_1, W1_2, W2_2)
    WPtrs wp;
    wp.p[0] = W1[0]; wp.p[1] = W2[0];
    wp.p[2] = W1[1]; wp.p[3] = W2[1];
    wp.p[4] = W1[2]; wp.p[5] = W2[2];
    wprep_kernel<<<(6 * 16384 + 255) / 256, 256>>>(wp, wimg);

    // CSR build (edges identical across layers)
    int NB = (M + 1023) / 1024;
    zero_cnt_kernel<<<(M + 255) / 256, 256>>>(cnt, M);
    hist_kernel<<<(E + 255) / 256, 256>>>(ei, cnt, E);
    scan1_kernel<<<NB, 256>>>(cnt, bsum, M);
    scan2_kernel<<<1, 128>>>(bsum, bbase, NB, off, M, E);
    scan3_kernel<<<NB, 256>>>(cnt, bbase, off, cur, M);
    fill_kernel<<<(E + 255) / 256, 256>>>(ei, cur, csr, E);

    int n4 = M * D / 4;
    int convBlocks = (n4 + 255) / 256;
    if (convBlocks > 4096) convBlocks = 4096;
    x2h_kernel<<<convBlocks, 256>>>(x, xh, n4);   // fp16 mirror of layer-0 input

    int nwarps = (M + 1) / 2;                     // 2 nodes per warp
    int aggBlocks = (nwarps * 32 + 255) / 256;
    int nt = (M + 63) / 64;
    int gemmGrid = (nt < GEMM_GRID) ? nt : GEMM_GRID;

    const float* curx = x;
    float* outs[3] = {t, t, (float*)d_out};

    for (int l = 0; l < 3; l++) {
        agg_csr_kernel<<<aggBlocks, 256>>>(curx, xh, off, csr, agg, M);
        gemm_mma_kernel<<<gemmGrid, 256, SMEM_TOTAL>>>(
            agg, wimg + (size_t)(2 * l) * IMG_ELEMS, b1[l], h, nullptr, M, nt);
        // GEMM2 writes fp32 out and (for layers 0,1) the fp16 mirror for next agg
        gemm_mma_kernel<<<gemmGrid, 256, SMEM_TOTAL>>>(
            h, wimg + (size_t)(2 * l + 1) * IMG_ELEMS, b2[l], outs[l],
            (l < 2) ? xh : nullptr, M, nt);
        curx = outs[l];
    }
}